// round 17
// baseline (speedup 1.0000x reference)
#include <cuda_runtime.h>
#include <cstdint>

// CenterLoss: loss = (1/B) * sum_b clamp(|x_b - c_{l_b}|^2, 1e-12, 1e12)
// (== |x|^2+|c|^2-2xc under the one-hot mask; 999e-12 constant is rel 1e-12,
//  below fp32 eps, dropped.)
//
// R13 (resubmit; prior round was container infra failure):
// 64 threads (2 warps) per row, 4 rows per 256-thread block, grid 4096.
// Rationale: R9 (MLP 8/warp) and R12 (MLP 16/warp) both ran 11.4-11.5us at
// 3.1TB/s -> per-warp MLP is not binding; total in-flight lines per SM is
// (~50). Small per-thread footprint (regs ~28 -> full occupancy) multiplies
// resident warps and keeps the LSU queue continuously fed.
// Finalize: memset node + one no-return atomicAdd (REDG) per block.

#define B_ROWS 16384
#define C_CLASSES 1000
#define D_DIM 512
#define THREADS 256
#define THREADS_PER_ROW 64
#define ROWS_PER_BLOCK (THREADS / THREADS_PER_ROW)          // 4
#define GRID_BLOCKS (B_ROWS / ROWS_PER_BLOCK)               // 4096

__global__ __launch_bounds__(THREADS, 8) void center_loss_rows(
    const float* __restrict__ x,
    const int* __restrict__ labels,
    const float* __restrict__ centers,
    float* __restrict__ out)
{
    __shared__ float warp_part[THREADS / 32];               // 8 warp partials
    const int warp_id = threadIdx.x >> 5;
    const int lane = threadIdx.x & 31;
    const int row_in_block = threadIdx.x / THREADS_PER_ROW; // 0..3
    const int sub = threadIdx.x & (THREADS_PER_ROW - 1);    // 0..63
    const int row = blockIdx.x * ROWS_PER_BLOCK + row_in_block;

    {
        int lbl = labels[row];
        lbl = (lbl < 0) ? 0 : ((lbl >= C_CLASSES) ? C_CLASSES - 1 : lbl);

        const float4* __restrict__ xr =
            reinterpret_cast<const float4*>(x + (size_t)row * D_DIM);
        const float4* __restrict__ cr =
            reinterpret_cast<const float4*>(centers + (size_t)lbl * D_DIM);

        // 512 floats / 64 threads = 8 floats = 2 float4 per thread.
        // All 4 loads independent, issued before any FMA.
        float4 x0 = xr[sub];
        float4 x1 = xr[sub + 64];
        float4 c0 = cr[sub];
        float4 c1 = cr[sub + 64];

        float d = 0.f, t;
        t = x0.x - c0.x; d = fmaf(t, t, d);
        t = x0.y - c0.y; d = fmaf(t, t, d);
        t = x0.z - c0.z; d = fmaf(t, t, d);
        t = x0.w - c0.w; d = fmaf(t, t, d);
        t = x1.x - c1.x; d = fmaf(t, t, d);
        t = x1.y - c1.y; d = fmaf(t, t, d);
        t = x1.z - c1.z; d = fmaf(t, t, d);
        t = x1.w - c1.w; d = fmaf(t, t, d);

        // warp reduce (5 shuffles) -> per-warp half-row partial
#pragma unroll
        for (int o = 16; o > 0; o >>= 1)
            d += __shfl_xor_sync(0xFFFFFFFFu, d, o);

        if (lane == 0) warp_part[warp_id] = d;
    }
    __syncthreads();

    // thread 0: combine half-row pairs, clamp PER ROW, sum 4 rows, one REDG
    if (threadIdx.x == 0) {
        float total = 0.f;
#pragma unroll
        for (int i = 0; i < ROWS_PER_BLOCK; i++) {
            float dr = warp_part[2 * i] + warp_part[2 * i + 1];
            dr = fminf(fmaxf(dr, 1e-12f), 1e12f);   // clamp per reference
            total += dr;
        }
        float contrib = (float)((double)total / (double)B_ROWS);
        atomicAdd(out, contrib);   // no-return -> REDG
    }
}

extern "C" void kernel_launch(void* const* d_in, const int* in_sizes, int n_in,
                              void* d_out, int out_size)
{
    const float* x = (const float*)d_in[0];
    const int* labels = (const int*)d_in[1];
    const float* centers = (const float*)d_in[2];
    float* out = (float*)d_out;

    cudaMemsetAsync(out, 0, sizeof(float));   // graph memset node
    center_loss_rows<<<GRID_BLOCKS, THREADS>>>(x, labels, centers, out);
}